// round 13
// baseline (speedup 1.0000x reference)
#include <cuda_runtime.h>
#include <cuda_fp16.h>
#include <math.h>
#include <stdint.h>

#define NTOK   8192
#define DMODEL 1024
#define DFF    4096
#define NEXP   8
#define MAXROWS 17408   // 136 tiles * 128
#define MAXTILES 136
#define RBLOCKS (NTOK / 8)

// ---------------- scratch (device symbols; never passed from host) -----------
__device__ __half g_x16[(size_t)NTOK * DMODEL];
__device__ __half g_w1t[(size_t)NEXP * DFF * DMODEL];   // [E][N=DFF][K=DMODEL]
__device__ __half g_w2t[(size_t)NEXP * DMODEL * DFF];   // [E][N=DMODEL][K=DFF]
__device__ __half g_h16[(size_t)MAXROWS * DFF];
__device__ float g_y[(size_t)MAXROWS * DMODEL];
__device__ int   g_assign_token[MAXROWS];
__device__ float g_assign_w[MAXROWS];
__device__ int   g_pos[NTOK * 2];
__device__ int   g_sel[NTOK * 2];
__device__ float g_wsel[NTOK * 2];
__device__ int   g_cnt[NEXP];
__device__ int   g_amax[NEXP];
__device__ float g_psum_part[RBLOCKS * NEXP];
__device__ int   g_fill[NEXP];
__device__ int   g_off[NEXP];
__device__ int   g_tile_expert[MAXTILES];
__device__ int   g_row_tiles;
__device__ int   g_wswap;   // 1 -> first 33M buffer is W2
__device__ int   g_gswap;   // 1 -> first 8192 buffer is b2

// ---------------- probes / init / router / prep / scatter --------------------
__global__ void k_probe(const float* __restrict__ A, const float* __restrict__ B,
                        int n, int which) {
    __shared__ float sa[256], sb[256];
    int tid = threadIdx.x;
    float a = 0.f, b = 0.f;
    for (int i = tid; i < n; i += 256) { a += fabsf(A[i]); b += fabsf(B[i]); }
    sa[tid] = a; sb[tid] = b;
    __syncthreads();
    for (int s = 128; s > 0; s >>= 1) {
        if (tid < s) { sa[tid] += sa[tid + s]; sb[tid] += sb[tid + s]; }
        __syncthreads();
    }
    if (tid == 0) {
        int f = (sa[0] < sb[0]) ? 1 : 0;
        if (which == 0) g_wswap = f; else g_gswap = f;
    }
}

__global__ void k_zero() {
    int i = blockIdx.x * blockDim.x + threadIdx.x;
    if (i < MAXROWS) { g_assign_token[i] = -1; g_assign_w[i] = 0.f; }
    if (i < NEXP) { g_cnt[i] = 0; g_amax[i] = 0; g_fill[i] = 0; }
}

// router: logits->softmax->top2 + aux stats; also emits x in fp16 (fused convx)
__global__ __launch_bounds__(256) void k_router(const float* __restrict__ x,
                                                const float* __restrict__ WgA,
                                                const float* __restrict__ WgB,
                                                const float* __restrict__ bg) {
    const float* Wg = g_gswap ? WgB : WgA;
    __shared__ float sW[NEXP][DMODEL];
    __shared__ float s_psum[NEXP];
    __shared__ int   s_amax[NEXP];
    __shared__ int   s_cnt[NEXP];
    int tid = threadIdx.x;
    for (int i = tid; i < DMODEL * NEXP; i += 256) sW[i & 7][i >> 3] = Wg[i];
    if (tid < NEXP) { s_psum[tid] = 0.f; s_amax[tid] = 0; s_cnt[tid] = 0; }
    __syncthreads();
    int warp = tid >> 5, lane = tid & 31;
    int t = blockIdx.x * 8 + warp;
    const float* xr = x + (size_t)t * DMODEL;
    __half* xo = g_x16 + (size_t)t * DMODEL;
    float acc[NEXP];
#pragma unroll
    for (int e = 0; e < NEXP; e++) acc[e] = 0.f;
    for (int j = 0; j < 32; j++) {
        float xv = xr[j * 32 + lane];
        xo[j * 32 + lane] = __float2half_rn(xv);
#pragma unroll
        for (int e = 0; e < NEXP; e++) acc[e] += xv * sW[e][j * 32 + lane];
    }
#pragma unroll
    for (int o = 16; o > 0; o >>= 1)
#pragma unroll
        for (int e = 0; e < NEXP; e++) acc[e] += __shfl_xor_sync(0xffffffffu, acc[e], o);
    if (lane == 0) {
        float l[NEXP], p[NEXP];
#pragma unroll
        for (int e = 0; e < NEXP; e++) l[e] = acc[e] + bg[e];
        float mx = l[0];
#pragma unroll
        for (int e = 1; e < NEXP; e++) mx = fmaxf(mx, l[e]);
        float s = 0.f;
#pragma unroll
        for (int e = 0; e < NEXP; e++) { p[e] = expf(l[e] - mx); s += p[e]; }
        float inv = 1.f / s;
#pragma unroll
        for (int e = 0; e < NEXP; e++) { p[e] *= inv; atomicAdd(&s_psum[e], p[e]); }
        int a1 = 0;
#pragma unroll
        for (int e = 1; e < NEXP; e++) if (p[e] > p[a1]) a1 = e;
        int a2 = -1;
#pragma unroll
        for (int e = 0; e < NEXP; e++) if (e != a1 && (a2 < 0 || p[e] > p[a2])) a2 = e;
        atomicAdd(&s_amax[a1], 1);
        atomicAdd(&s_cnt[a1], 1);
        atomicAdd(&s_cnt[a2], 1);
        float ws = 1.f / (p[a1] + p[a2]);
        g_sel[t * 2 + 0] = a1;  g_wsel[t * 2 + 0] = p[a1] * ws;
        g_sel[t * 2 + 1] = a2;  g_wsel[t * 2 + 1] = p[a2] * ws;
    }
    __syncthreads();
    if (tid < NEXP) {
        g_psum_part[blockIdx.x * NEXP + tid] = s_psum[tid];
        atomicAdd(&g_amax[tid], s_amax[tid]);
        atomicAdd(&g_cnt[tid], s_cnt[tid]);
    }
}

__global__ void k_prep(float* d_out, int out_size) {
    if (threadIdx.x == 0 && blockIdx.x == 0) {
        int off = 0, tiles = 0;
        for (int e = 0; e < NEXP; e++) {
            g_off[e] = off;
            int nt = (g_cnt[e] + 127) >> 7;
            for (int i = 0; i < nt; i++) g_tile_expert[tiles++] = e;
            off += nt * 128;
        }
        g_row_tiles = tiles;
        float aux = 0.f;
        for (int e = 0; e < NEXP; e++) {
            float pm = 0.f;
            for (int b = 0; b < RBLOCKS; b++) pm += g_psum_part[b * NEXP + e];
            aux += (pm / (float)NTOK) * ((float)g_amax[e] / (float)NTOK);
        }
        aux *= (float)NEXP;
        if (out_size > NTOK * DMODEL) d_out[(size_t)NTOK * DMODEL] = aux;
    }
}

__global__ void k_scatter() {
    int i = blockIdx.x * blockDim.x + threadIdx.x;
    if (i >= NTOK * 2) return;
    int t = i >> 1;
    int e = g_sel[i];
    int p = atomicAdd(&g_fill[e], 1);
    int row = g_off[e] + p;
    g_assign_token[row] = t;
    g_assign_w[row] = g_wsel[i];
    g_pos[i] = row;
}

// transpose W[E][K][N] fp32 -> [E][N][K] fp16
template <bool PHASE1>
__global__ __launch_bounds__(256) void k_wtrans(const float* __restrict__ WA,
                                                const float* __restrict__ WB) {
    constexpr int K = PHASE1 ? DMODEL : DFF;
    constexpr int N = PHASE1 ? DFF : DMODEL;
    const float* W = PHASE1 ? (g_wswap ? WB : WA) : (g_wswap ? WA : WB);
    __half* O = PHASE1 ? g_w1t : g_w2t;
    int e = blockIdx.z;
    int n0 = blockIdx.x * 32, k0 = blockIdx.y * 32;
    __shared__ float t[32][33];
    int tx = threadIdx.x & 31, ty = threadIdx.x >> 5;
    const float* Wp = W + (size_t)e * K * N;
#pragma unroll
    for (int j = 0; j < 4; j++) {
        int k = ty + j * 8;
        t[k][tx] = Wp[(size_t)(k0 + k) * N + n0 + tx];
    }
    __syncthreads();
#pragma unroll
    for (int j = 0; j < 4; j++) {
        int n = ty + j * 8;
        size_t o = ((size_t)e * N + n0 + n) * K + k0 + tx;
        O[o] = __float2half_rn(t[tx][n]);
    }
}

// ---------------- PTX helpers ------------------------------------------------
__device__ __forceinline__ uint32_t smem_u32(const void* p) {
    uint32_t a;
    asm("{ .reg .u64 t; cvta.to.shared.u64 t, %1; cvt.u32.u64 %0, t; }" : "=r"(a) : "l"(p));
    return a;
}
__device__ __forceinline__ void cp16(uint32_t s, const void* g, uint32_t srcsize) {
    asm volatile("cp.async.cg.shared.global [%0], [%1], 16, %2;"
                 :: "r"(s), "l"(g), "r"(srcsize) : "memory");
}
#define CP_COMMIT() asm volatile("cp.async.commit_group;" ::: "memory")
#define CP_WAIT2()  asm volatile("cp.async.wait_group 2;" ::: "memory")
#define CP_WAIT0()  asm volatile("cp.async.wait_group 0;" ::: "memory")

__device__ __forceinline__ void ldm4(uint32_t& r0, uint32_t& r1, uint32_t& r2,
                                     uint32_t& r3, uint32_t addr) {
    asm volatile("ldmatrix.sync.aligned.m8n8.x4.shared.b16 {%0,%1,%2,%3}, [%4];"
                 : "=r"(r0), "=r"(r1), "=r"(r2), "=r"(r3) : "r"(addr));
}
__device__ __forceinline__ void mma16816(float* c, const uint32_t* a,
                                         uint32_t b0, uint32_t b1) {
    asm volatile(
        "mma.sync.aligned.m16n8k16.row.col.f32.f16.f16.f32 "
        "{%0,%1,%2,%3}, {%4,%5,%6,%7}, {%8,%9}, {%0,%1,%2,%3};"
        : "+f"(c[0]), "+f"(c[1]), "+f"(c[2]), "+f"(c[3])
        : "r"(a[0]), "r"(a[1]), "r"(a[2]), "r"(a[3]), "r"(b0), "r"(b1));
}

// ---------------- fp16 tensor-core grouped GEMM ------------------------------
// CTA 128x128, 4 warps (2x2), warp tile 64x64, BK=32, 3-stage cp.async,
// ldmatrix fragment loads (8 ldm4 : 32 mma per k16-step = 1:4 intensity).
// smem row stride = 40 fp16 = 80 bytes (conflict-free ldmatrix phases).
#define ROWB 80
#define OFF_A 0
#define OFF_B 10240
#define BUF_B 20480
#define NSTAGE 3
#define SMEM_TOTAL_MMA (NSTAGE * BUF_B)   // 61440

template <bool PHASE1>
__global__ __launch_bounds__(128, 2) void k_mma(const float* __restrict__ BiasA,
                                                const float* __restrict__ BiasB) {
    constexpr int KDIM = PHASE1 ? DMODEL : DFF;
    constexpr int NDIM = PHASE1 ? DFF : DMODEL;
    constexpr int NC = KDIM / 32;
    int tileRow = blockIdx.x;
    if (tileRow >= g_row_tiles) return;
    int e = g_tile_expert[tileRow];
    int row0 = tileRow * 128;
    int col0 = blockIdx.y * 128;

    extern __shared__ char dsm[];
    __shared__ int s_tok[128];
    uint32_t smb = smem_u32(dsm);

    int tid = threadIdx.x;
    int w = tid >> 5, lane = tid & 31;
    int grp = lane >> 2, qid = lane & 3;
    int wr = w >> 1, wc = w & 1;          // 2x2 warp grid
    int m0 = wr * 64, n0 = wc * 64;

    s_tok[tid] = g_assign_token[row0 + tid];

    const __half* A_base = PHASE1 ? g_x16 : g_h16;
    const __half* B_base = PHASE1 ? g_w1t : g_w2t;

    int lrow = tid;                        // one full 64B row per thread

    float c[4][8][4];
#pragma unroll
    for (int i = 0; i < 4; i++)
#pragma unroll
        for (int j = 0; j < 8; j++)
#pragma unroll
            for (int q = 0; q < 4; q++) c[i][j][q] = 0.f;

    __syncthreads();                       // s_tok visible

    // ---- chunk loader: 4x16B per array per thread (full 64B rows) ----
    auto load_chunk = [&](int cidx, int buf) {
        int k0 = cidx * 32;
        uint32_t sb = smb + buf * BUF_B;
        uint32_t so = (uint32_t)lrow * ROWB;
        size_t asrc; uint32_t vs = 16;
        if (PHASE1) {
            int tok = s_tok[lrow];
            if (tok < 0) { tok = 0; vs = 0; }
            asrc = (size_t)tok * KDIM + k0;
        } else {
            asrc = (size_t)(row0 + lrow) * KDIM + k0;
        }
#pragma unroll
        for (int s = 0; s < 4; s++)
            cp16(sb + OFF_A + so + s * 16, A_base + asrc + s * 8, vs);
        size_t bsrc = ((size_t)e * NDIM + col0 + lrow) * KDIM + k0;
#pragma unroll
        for (int s = 0; s < 4; s++)
            cp16(sb + OFF_B + so + s * 16, B_base + bsrc + s * 8, 16);
    };

    load_chunk(0, 0);
    CP_COMMIT();
    load_chunk(1, 1);
    CP_COMMIT();

    // per-lane ldmatrix address pieces
    uint32_t a_row = (uint32_t)(lane & 15);
    uint32_t a_koff = (uint32_t)((lane >> 4) * 8);
    uint32_t b_rowoff = (uint32_t)(((lane >> 4) & 1) * 8 + (lane & 7));
    uint32_t b_koff = (uint32_t)(((lane >> 3) & 1) * 8);

    for (int cidx = 0; cidx < NC; cidx++) {
        if (cidx + 2 < NC) load_chunk(cidx + 2, (cidx + 2) % NSTAGE);
        CP_COMMIT();           // uniform: one group per iteration (may be empty)
        CP_WAIT2();            // chunk cidx resident
        __syncthreads();

        uint32_t sb = smb + (cidx % NSTAGE) * BUF_B;
#pragma unroll
        for (int ks = 0; ks < 32; ks += 16) {
            uint32_t a[4][4];
#pragma unroll
            for (int mt = 0; mt < 4; mt++) {
                uint32_t ad = sb + OFF_A + (uint32_t)(m0 + mt * 16 + a_row) * ROWB
                            + (ks + a_koff) * 2;
                ldm4(a[mt][0], a[mt][1], a[mt][2], a[mt][3], ad);
            }
            uint32_t b[8][2];
#pragma unroll
            for (int np = 0; np < 4; np++) {
                uint32_t bd = sb + OFF_B + (uint32_t)(n0 + np * 16 + b_rowoff) * ROWB
                            + (ks + b_koff) * 2;
                ldm4(b[2 * np][0], b[2 * np][1], b[2 * np + 1][0],
                     b[2 * np + 1][1], bd);
            }
#pragma unroll
            for (int nt = 0; nt < 8; nt++)
#pragma unroll
                for (int mt = 0; mt < 4; mt++)
                    mma16816(c[mt][nt], a[mt], b[nt][0], b[nt][1]);
        }
        __syncthreads();   // all frag reads done before buffer reuse
    }
    CP_WAIT0();

    // ---- epilogue ----
    const float* Bias = PHASE1 ? BiasA : (g_gswap ? BiasA : BiasB);
#pragma unroll
    for (int mt = 0; mt < 4; mt++) {
        int rA = row0 + m0 + mt * 16 + grp;   // rows rA, rA+8
        float sc0 = PHASE1 ? 1.f : g_assign_w[rA];
        float sc1 = PHASE1 ? 1.f : g_assign_w[rA + 8];
#pragma unroll
        for (int nt = 0; nt < 8; nt++) {
            int col = col0 + n0 + nt * 8 + qid * 2;
            float b0 = Bias[(size_t)e * NDIM + col];
            float b1v = Bias[(size_t)e * NDIM + col + 1];
            float v00 = c[mt][nt][0] + b0, v01 = c[mt][nt][1] + b1v;
            float v10 = c[mt][nt][2] + b0, v11 = c[mt][nt][3] + b1v;
            if (PHASE1) {
                v00 = 0.5f * v00 * (1.f + erff(v00 * 0.70710678118654752f));
                v01 = 0.5f * v01 * (1.f + erff(v01 * 0.70710678118654752f));
                v10 = 0.5f * v10 * (1.f + erff(v10 * 0.70710678118654752f));
                v11 = 0.5f * v11 * (1.f + erff(v11 * 0.70710678118654752f));
                size_t o0 = (size_t)rA * DFF + col;
                size_t o1 = (size_t)(rA + 8) * DFF + col;
                *(__half2*)(g_h16 + o0) = __halves2half2(__float2half_rn(v00), __float2half_rn(v01));
                *(__half2*)(g_h16 + o1) = __halves2half2(__float2half_rn(v10), __float2half_rn(v11));
            } else {
                size_t o0 = (size_t)rA * DMODEL + col;
                size_t o1 = (size_t)(rA + 8) * DMODEL + col;
                *(float2*)(g_y + o0) = make_float2(v00 * sc0, v01 * sc0);
                *(float2*)(g_y + o1) = make_float2(v10 * sc1, v11 * sc1);
            }
        }
    }
}

// ---------------- combine -----------------------------------------------------
__global__ void k_combine(float* __restrict__ out) {
    int t = blockIdx.x;
    int c = threadIdx.x;
    int p0 = g_pos[t * 2 + 0];
    int p1 = g_pos[t * 2 + 1];
    const float4* y0 = (const float4*)(g_y + (size_t)p0 * DMODEL);
    const float4* y1 = (const float4*)(g_y + (size_t)p1 * DMODEL);
    float4 a = y0[c], b = y1[c];
    ((float4*)(out + (size_t)t * DMODEL))[c] =
        make_float4(a.x + b.x, a.y + b.y, a.z + b.z, a.w + b.w);
}

// ---------------- launch -----------------------------------------------------
extern "C" void kernel_launch(void* const* d_in, const int* in_sizes, int n_in,
                              void* d_out, int out_size) {
    const float *x = nullptr, *bg = nullptr, *b1 = nullptr;
    const float *w33[2] = {nullptr, nullptr};
    const float *g8k[2] = {nullptr, nullptr};
    int n33 = 0, n8k = 0;
    for (int i = 0; i < n_in; i++) {
        int sz = in_sizes[i];
        const float* p = (const float*)d_in[i];
        if      (sz == NTOK * DMODEL)        x  = p;
        else if (sz == NEXP)                 bg = p;
        else if (sz == NEXP * DFF)           b1 = p;
        else if (sz == NEXP * DMODEL * DFF)  { if (n33 < 2) w33[n33++] = p; }
        else if (sz == DMODEL * NEXP)        { if (n8k < 2) g8k[n8k++] = p; }
    }
    float* out = (float*)d_out;

    cudaFuncSetAttribute(k_mma<true>,  cudaFuncAttributeMaxDynamicSharedMemorySize, SMEM_TOTAL_MMA);
    cudaFuncSetAttribute(k_mma<false>, cudaFuncAttributeMaxDynamicSharedMemorySize, SMEM_TOTAL_MMA);

    k_probe<<<1, 256>>>(w33[0], w33[1], 4096, 0);
    k_probe<<<1, 256>>>(g8k[0], g8k[1], 8192, 1);

    k_zero<<<(MAXROWS + 255) / 256, 256>>>();
    k_router<<<RBLOCKS, 256>>>(x, g8k[0], g8k[1], bg);
    k_prep<<<1, 32>>>(out, out_size);
    k_scatter<<<(NTOK * 2 + 255) / 256, 256>>>();

    {   // W1: [E][1024][4096] -> [E][4096][1024]
        dim3 g(DFF / 32, DMODEL / 32, NEXP);
        k_wtrans<true><<<g, 256>>>(w33[0], w33[1]);
    }
    {   // W2: [E][4096][1024] -> [E][1024][4096]
        dim3 g(DMODEL / 32, DFF / 32, NEXP);
        k_wtrans<false><<<g, 256>>>(w33[0], w33[1]);
    }

    {   // GEMM1: h = gelu(gather(x) @ W1 + b1)
        dim3 grid(MAXTILES, DFF / 128);
        k_mma<true><<<grid, 128, SMEM_TOTAL_MMA>>>(b1, b1);
    }
    {   // GEMM2: y = (h @ W2 + b2) * w
        dim3 grid(MAXTILES, DMODEL / 128);
        k_mma<false><<<grid, 128, SMEM_TOTAL_MMA>>>(g8k[0], g8k[1]);
    }
    k_combine<<<NTOK, 256>>>(out);
}

// round 15
// speedup vs baseline: 1.1746x; 1.1746x over previous
#include <cuda_runtime.h>
#include <cuda_fp16.h>
#include <math.h>
#include <stdint.h>

#define NTOK   8192
#define DMODEL 1024
#define DFF    4096
#define NEXP   8
#define MAXROWS 17408   // 136 tiles * 128
#define MAXTILES 136
#define RBLOCKS (NTOK / 8)

// ---------------- scratch (device symbols; never passed from host) -----------
__device__ __half g_x16[(size_t)NTOK * DMODEL];
__device__ __half g_w1t[(size_t)NEXP * DFF * DMODEL];   // [E][N=DFF][K=DMODEL]
__device__ __half g_w2t[(size_t)NEXP * DMODEL * DFF];   // [E][N=DMODEL][K=DFF]
__device__ __half g_h16[(size_t)MAXROWS * DFF];
__device__ float g_y[(size_t)MAXROWS * DMODEL];
__device__ int   g_assign_token[MAXROWS];
__device__ float g_assign_w[MAXROWS];
__device__ int   g_pos[NTOK * 2];
__device__ int   g_sel[NTOK * 2];
__device__ float g_wsel[NTOK * 2];
__device__ int   g_cnt[NEXP];
__device__ int   g_amax[NEXP];
__device__ float g_psum_part[RBLOCKS * NEXP];
__device__ int   g_fill[NEXP];
__device__ int   g_off[NEXP];
__device__ int   g_tile_expert[MAXTILES];
__device__ int   g_row_tiles;
__device__ int   g_wswap;   // 1 -> first 33M buffer is W2
__device__ int   g_gswap;   // 1 -> first 8192 buffer is b2

// ---------------- probes / init / router / prep / scatter --------------------
__global__ void k_probe(const float* __restrict__ A, const float* __restrict__ B,
                        int n, int which) {
    __shared__ float sa[256], sb[256];
    int tid = threadIdx.x;
    float a = 0.f, b = 0.f;
    for (int i = tid; i < n; i += 256) { a += fabsf(A[i]); b += fabsf(B[i]); }
    sa[tid] = a; sb[tid] = b;
    __syncthreads();
    for (int s = 128; s > 0; s >>= 1) {
        if (tid < s) { sa[tid] += sa[tid + s]; sb[tid] += sb[tid + s]; }
        __syncthreads();
    }
    if (tid == 0) {
        int f = (sa[0] < sb[0]) ? 1 : 0;
        if (which == 0) g_wswap = f; else g_gswap = f;
    }
}

__global__ void k_zero() {
    int i = blockIdx.x * blockDim.x + threadIdx.x;
    if (i < MAXROWS) { g_assign_token[i] = -1; g_assign_w[i] = 0.f; }
    if (i < NEXP) { g_cnt[i] = 0; g_amax[i] = 0; g_fill[i] = 0; }
}

// router: logits->softmax->top2 + aux stats; also emits x in fp16 (fused convx)
__global__ __launch_bounds__(256) void k_router(const float* __restrict__ x,
                                                const float* __restrict__ WgA,
                                                const float* __restrict__ WgB,
                                                const float* __restrict__ bg) {
    const float* Wg = g_gswap ? WgB : WgA;
    __shared__ float sW[NEXP][DMODEL];
    __shared__ float s_psum[NEXP];
    __shared__ int   s_amax[NEXP];
    __shared__ int   s_cnt[NEXP];
    int tid = threadIdx.x;
    for (int i = tid; i < DMODEL * NEXP; i += 256) sW[i & 7][i >> 3] = Wg[i];
    if (tid < NEXP) { s_psum[tid] = 0.f; s_amax[tid] = 0; s_cnt[tid] = 0; }
    __syncthreads();
    int warp = tid >> 5, lane = tid & 31;
    int t = blockIdx.x * 8 + warp;
    const float* xr = x + (size_t)t * DMODEL;
    __half* xo = g_x16 + (size_t)t * DMODEL;
    float acc[NEXP];
#pragma unroll
    for (int e = 0; e < NEXP; e++) acc[e] = 0.f;
    for (int j = 0; j < 32; j++) {
        float xv = xr[j * 32 + lane];
        xo[j * 32 + lane] = __float2half_rn(xv);
#pragma unroll
        for (int e = 0; e < NEXP; e++) acc[e] += xv * sW[e][j * 32 + lane];
    }
#pragma unroll
    for (int o = 16; o > 0; o >>= 1)
#pragma unroll
        for (int e = 0; e < NEXP; e++) acc[e] += __shfl_xor_sync(0xffffffffu, acc[e], o);
    if (lane == 0) {
        float l[NEXP], p[NEXP];
#pragma unroll
        for (int e = 0; e < NEXP; e++) l[e] = acc[e] + bg[e];
        float mx = l[0];
#pragma unroll
        for (int e = 1; e < NEXP; e++) mx = fmaxf(mx, l[e]);
        float s = 0.f;
#pragma unroll
        for (int e = 0; e < NEXP; e++) { p[e] = expf(l[e] - mx); s += p[e]; }
        float inv = 1.f / s;
#pragma unroll
        for (int e = 0; e < NEXP; e++) { p[e] *= inv; atomicAdd(&s_psum[e], p[e]); }
        int a1 = 0;
#pragma unroll
        for (int e = 1; e < NEXP; e++) if (p[e] > p[a1]) a1 = e;
        int a2 = -1;
#pragma unroll
        for (int e = 0; e < NEXP; e++) if (e != a1 && (a2 < 0 || p[e] > p[a2])) a2 = e;
        atomicAdd(&s_amax[a1], 1);
        atomicAdd(&s_cnt[a1], 1);
        atomicAdd(&s_cnt[a2], 1);
        float ws = 1.f / (p[a1] + p[a2]);
        g_sel[t * 2 + 0] = a1;  g_wsel[t * 2 + 0] = p[a1] * ws;
        g_sel[t * 2 + 1] = a2;  g_wsel[t * 2 + 1] = p[a2] * ws;
    }
    __syncthreads();
    if (tid < NEXP) {
        g_psum_part[blockIdx.x * NEXP + tid] = s_psum[tid];
        atomicAdd(&g_amax[tid], s_amax[tid]);
        atomicAdd(&g_cnt[tid], s_cnt[tid]);
    }
}

__global__ void k_prep(float* d_out, int out_size) {
    if (threadIdx.x == 0 && blockIdx.x == 0) {
        int off = 0, tiles = 0;
        for (int e = 0; e < NEXP; e++) {
            g_off[e] = off;
            int nt = (g_cnt[e] + 127) >> 7;
            for (int i = 0; i < nt; i++) g_tile_expert[tiles++] = e;
            off += nt * 128;
        }
        g_row_tiles = tiles;
        float aux = 0.f;
        for (int e = 0; e < NEXP; e++) {
            float pm = 0.f;
            for (int b = 0; b < RBLOCKS; b++) pm += g_psum_part[b * NEXP + e];
            aux += (pm / (float)NTOK) * ((float)g_amax[e] / (float)NTOK);
        }
        aux *= (float)NEXP;
        if (out_size > NTOK * DMODEL) d_out[(size_t)NTOK * DMODEL] = aux;
    }
}

__global__ void k_scatter() {
    int i = blockIdx.x * blockDim.x + threadIdx.x;
    if (i >= NTOK * 2) return;
    int t = i >> 1;
    int e = g_sel[i];
    int p = atomicAdd(&g_fill[e], 1);
    int row = g_off[e] + p;
    g_assign_token[row] = t;
    g_assign_w[row] = g_wsel[i];
    g_pos[i] = row;
}

// transpose W[E][K][N] fp32 -> [E][N][K] fp16, vectorized half2 writes.
// Tile: 64 k x 32 n per block, 256 threads.
template <bool PHASE1>
__global__ __launch_bounds__(256) void k_wtrans(const float* __restrict__ WA,
                                                const float* __restrict__ WB) {
    constexpr int K = PHASE1 ? DMODEL : DFF;
    constexpr int N = PHASE1 ? DFF : DMODEL;
    const float* W = PHASE1 ? (g_wswap ? WB : WA) : (g_wswap ? WA : WB);
    __half* O = PHASE1 ? g_w1t : g_w2t;
    int e = blockIdx.z;
    int n0 = blockIdx.x * 32, k0 = blockIdx.y * 64;
    __shared__ float t[64][33];
    int tid = threadIdx.x;
    int tx = tid & 31, ty = tid >> 5;          // tx: n, ty: k-group (8)
    const float* Wp = W + (size_t)e * K * N;
#pragma unroll
    for (int j = 0; j < 8; j++) {
        int k = ty + j * 8;
        t[k][tx] = Wp[(size_t)(k0 + k) * N + n0 + tx];
    }
    __syncthreads();
    // write: n = tid>>3 (32 rows), k covers 8 contiguous from (tid&7)*8
    int n = tid >> 3;
    int kb = (tid & 7) * 8;
    __half* Orow = O + ((size_t)e * N + n0 + n) * K + k0 + kb;
#pragma unroll
    for (int j = 0; j < 4; j++) {
        float v0 = t[kb + 2 * j][n];
        float v1 = t[kb + 2 * j + 1][n];
        *(__half2*)(Orow + 2 * j) = __halves2half2(__float2half_rn(v0), __float2half_rn(v1));
    }
}

// ---------------- PTX helpers ------------------------------------------------
__device__ __forceinline__ uint32_t smem_u32(const void* p) {
    uint32_t a;
    asm("{ .reg .u64 t; cvta.to.shared.u64 t, %1; cvt.u32.u64 %0, t; }" : "=r"(a) : "l"(p));
    return a;
}
__device__ __forceinline__ void cp16(uint32_t s, const void* g, uint32_t srcsize) {
    asm volatile("cp.async.cg.shared.global [%0], [%1], 16, %2;"
                 :: "r"(s), "l"(g), "r"(srcsize) : "memory");
}
#define CP_COMMIT() asm volatile("cp.async.commit_group;" ::: "memory")
#define CP_WAIT2()  asm volatile("cp.async.wait_group 2;" ::: "memory")
#define CP_WAIT0()  asm volatile("cp.async.wait_group 0;" ::: "memory")

__device__ __forceinline__ void ldm4(uint32_t& r0, uint32_t& r1, uint32_t& r2,
                                     uint32_t& r3, uint32_t addr) {
    asm volatile("ldmatrix.sync.aligned.m8n8.x4.shared.b16 {%0,%1,%2,%3}, [%4];"
                 : "=r"(r0), "=r"(r1), "=r"(r2), "=r"(r3) : "r"(addr));
}
__device__ __forceinline__ void mma16816(float* c, const uint32_t* a,
                                         uint32_t b0, uint32_t b1) {
    asm volatile(
        "mma.sync.aligned.m16n8k16.row.col.f32.f16.f16.f32 "
        "{%0,%1,%2,%3}, {%4,%5,%6,%7}, {%8,%9}, {%0,%1,%2,%3};"
        : "+f"(c[0]), "+f"(c[1]), "+f"(c[2]), "+f"(c[3])
        : "r"(a[0]), "r"(a[1]), "r"(a[2]), "r"(a[3]), "r"(b0), "r"(b1));
}

// ---------------- fp16 tensor-core grouped GEMM (R11-proven config) ----------
// CTA 128x128, 8 warps (4x2), warp tile 32x64, BK=32, 3-stage cp.async,
// ldmatrix fragment loads. smem row stride = 40 fp16 = 80 bytes.
#define ROWB 80
#define OFF_A 0
#define OFF_B 10240
#define BUF_B 20480
#define NSTAGE 3
#define SMEM_TOTAL_MMA (NSTAGE * BUF_B)   // 61440

template <bool PHASE1>
__global__ __launch_bounds__(256) void k_mma(const float* __restrict__ BiasA,
                                             const float* __restrict__ BiasB) {
    constexpr int KDIM = PHASE1 ? DMODEL : DFF;
    constexpr int NDIM = PHASE1 ? DFF : DMODEL;
    constexpr int NC = KDIM / 32;
    int tileRow = blockIdx.x;
    if (tileRow >= g_row_tiles) return;
    int e = g_tile_expert[tileRow];
    int row0 = tileRow * 128;
    int col0 = blockIdx.y * 128;

    extern __shared__ char dsm[];
    __shared__ int s_tok[128];
    uint32_t smb = smem_u32(dsm);

    int tid = threadIdx.x;
    int w = tid >> 5, lane = tid & 31;
    int grp = lane >> 2, qid = lane & 3;
    int wr = w >> 1, wc = w & 1;
    int m0 = wr * 32, n0 = wc * 64;

    if (tid < 128) s_tok[tid] = g_assign_token[row0 + tid];

    const __half* A_base = PHASE1 ? g_x16 : g_h16;
    const __half* B_base = PHASE1 ? g_w1t : g_w2t;

    int lrow = tid >> 1;               // 0..127
    int lk   = (tid & 1) * 16;         // element offset 0 or 16

    float c[2][8][4];
#pragma unroll
    for (int i = 0; i < 2; i++)
#pragma unroll
        for (int j = 0; j < 8; j++)
#pragma unroll
            for (int q = 0; q < 4; q++) c[i][j][q] = 0.f;

    __syncthreads();                   // s_tok visible before gather loads

    // ---- chunk loader: 2x16B per array per thread (full 64B rows) ----
    auto load_chunk = [&](int cidx, int buf) {
        int k0 = cidx * 32;
        uint32_t sb = smb + buf * BUF_B;
        uint32_t so = (uint32_t)lrow * ROWB + lk * 2;   // byte offset 0 or 32
        size_t asrc; uint32_t vs = 16;
        if (PHASE1) {
            int tok = s_tok[lrow];
            if (tok < 0) { tok = 0; vs = 0; }
            asrc = (size_t)tok * KDIM + k0 + lk;
        } else {
            asrc = (size_t)(row0 + lrow) * KDIM + k0 + lk;
        }
        cp16(sb + OFF_A + so,      A_base + asrc,     vs);
        cp16(sb + OFF_A + so + 16, A_base + asrc + 8, vs);
        size_t bsrc = ((size_t)e * NDIM + col0 + lrow) * KDIM + k0 + lk;
        cp16(sb + OFF_B + so,      B_base + bsrc,     16);
        cp16(sb + OFF_B + so + 16, B_base + bsrc + 8, 16);
    };

    load_chunk(0, 0);
    CP_COMMIT();
    load_chunk(1, 1);
    CP_COMMIT();

    // per-lane ldmatrix address pieces
    uint32_t a_row = (uint32_t)(lane & 15);
    uint32_t a_koff = (uint32_t)((lane >> 4) * 8);
    uint32_t b_rowoff = (uint32_t)(((lane >> 4) & 1) * 8 + (lane & 7));
    uint32_t b_koff = (uint32_t)(((lane >> 3) & 1) * 8);

    for (int cidx = 0; cidx < NC; cidx++) {
        if (cidx + 2 < NC) load_chunk(cidx + 2, (cidx + 2) % NSTAGE);
        CP_COMMIT();           // uniform: one group per iteration (may be empty)
        CP_WAIT2();            // chunk cidx resident
        __syncthreads();

        uint32_t sb = smb + (cidx % NSTAGE) * BUF_B;
#pragma unroll
        for (int ks = 0; ks < 32; ks += 16) {
            uint32_t a[2][4];
#pragma unroll
            for (int mt = 0; mt < 2; mt++) {
                uint32_t ad = sb + OFF_A + (uint32_t)(m0 + mt * 16 + a_row) * ROWB
                            + (ks + a_koff) * 2;
                ldm4(a[mt][0], a[mt][1], a[mt][2], a[mt][3], ad);
            }
            uint32_t b[8][2];
#pragma unroll
            for (int np = 0; np < 4; np++) {
                uint32_t bd = sb + OFF_B + (uint32_t)(n0 + np * 16 + b_rowoff) * ROWB
                            + (ks + b_koff) * 2;
                ldm4(b[2 * np][0], b[2 * np][1], b[2 * np + 1][0],
                     b[2 * np + 1][1], bd);
            }
#pragma unroll
            for (int nt = 0; nt < 8; nt++)
#pragma unroll
                for (int mt = 0; mt < 2; mt++)
                    mma16816(c[mt][nt], a[mt], b[nt][0], b[nt][1]);
        }
        __syncthreads();   // all frag reads done before buffer reuse
    }
    CP_WAIT0();

    // ---- epilogue ----
    const float* Bias = PHASE1 ? BiasA : (g_gswap ? BiasA : BiasB);
#pragma unroll
    for (int mt = 0; mt < 2; mt++) {
        int rA = row0 + m0 + mt * 16 + grp;
        float sc0 = PHASE1 ? 1.f : g_assign_w[rA];
        float sc1 = PHASE1 ? 1.f : g_assign_w[rA + 8];
#pragma unroll
        for (int nt = 0; nt < 8; nt++) {
            int col = col0 + n0 + nt * 8 + qid * 2;
            float b0 = Bias[(size_t)e * NDIM + col];
            float b1v = Bias[(size_t)e * NDIM + col + 1];
            float v00 = c[mt][nt][0] + b0, v01 = c[mt][nt][1] + b1v;
            float v10 = c[mt][nt][2] + b0, v11 = c[mt][nt][3] + b1v;
            if (PHASE1) {
                v00 = 0.5f * v00 * (1.f + erff(v00 * 0.70710678118654752f));
                v01 = 0.5f * v01 * (1.f + erff(v01 * 0.70710678118654752f));
                v10 = 0.5f * v10 * (1.f + erff(v10 * 0.70710678118654752f));
                v11 = 0.5f * v11 * (1.f + erff(v11 * 0.70710678118654752f));
                size_t o0 = (size_t)rA * DFF + col;
                size_t o1 = (size_t)(rA + 8) * DFF + col;
                *(__half2*)(g_h16 + o0) = __halves2half2(__float2half_rn(v00), __float2half_rn(v01));
                *(__half2*)(g_h16 + o1) = __halves2half2(__float2half_rn(v10), __float2half_rn(v11));
            } else {
                size_t o0 = (size_t)rA * DMODEL + col;
                size_t o1 = (size_t)(rA + 8) * DMODEL + col;
                *(float2*)(g_y + o0) = make_float2(v00 * sc0, v01 * sc0);
                *(float2*)(g_y + o1) = make_float2(v10 * sc1, v11 * sc1);
            }
        }
    }
}

// ---------------- combine -----------------------------------------------------
__global__ void k_combine(float* __restrict__ out) {
    int t = blockIdx.x;
    int c = threadIdx.x;
    int p0 = g_pos[t * 2 + 0];
    int p1 = g_pos[t * 2 + 1];
    const float4* y0 = (const float4*)(g_y + (size_t)p0 * DMODEL);
    const float4* y1 = (const float4*)(g_y + (size_t)p1 * DMODEL);
    float4 a = y0[c], b = y1[c];
    ((float4*)(out + (size_t)t * DMODEL))[c] =
        make_float4(a.x + b.x, a.y + b.y, a.z + b.z, a.w + b.w);
}

// ---------------- launch -----------------------------------------------------
extern "C" void kernel_launch(void* const* d_in, const int* in_sizes, int n_in,
                              void* d_out, int out_size) {
    const float *x = nullptr, *bg = nullptr, *b1 = nullptr;
    const float *w33[2] = {nullptr, nullptr};
    const float *g8k[2] = {nullptr, nullptr};
    int n33 = 0, n8k = 0;
    for (int i = 0; i < n_in; i++) {
        int sz = in_sizes[i];
        const float* p = (const float*)d_in[i];
        if      (sz == NTOK * DMODEL)        x  = p;
        else if (sz == NEXP)                 bg = p;
        else if (sz == NEXP * DFF)           b1 = p;
        else if (sz == NEXP * DMODEL * DFF)  { if (n33 < 2) w33[n33++] = p; }
        else if (sz == DMODEL * NEXP)        { if (n8k < 2) g8k[n8k++] = p; }
    }
    float* out = (float*)d_out;

    cudaFuncSetAttribute(k_mma<true>,  cudaFuncAttributeMaxDynamicSharedMemorySize, SMEM_TOTAL_MMA);
    cudaFuncSetAttribute(k_mma<false>, cudaFuncAttributeMaxDynamicSharedMemorySize, SMEM_TOTAL_MMA);

    k_probe<<<1, 256>>>(w33[0], w33[1], 4096, 0);
    k_probe<<<1, 256>>>(g8k[0], g8k[1], 8192, 1);

    k_zero<<<(MAXROWS + 255) / 256, 256>>>();
    k_router<<<RBLOCKS, 256>>>(x, g8k[0], g8k[1], bg);
    k_prep<<<1, 32>>>(out, out_size);
    k_scatter<<<(NTOK * 2 + 255) / 256, 256>>>();

    {   // W1: [E][1024][4096] -> [E][4096][1024]
        dim3 g(DFF / 32, DMODEL / 64, NEXP);
        k_wtrans<true><<<g, 256>>>(w33[0], w33[1]);
    }
    {   // W2: [E][4096][1024] -> [E][1024][4096]
        dim3 g(DMODEL / 32, DFF / 64, NEXP);
        k_wtrans<false><<<g, 256>>>(w33[0], w33[1]);
    }

    {   // GEMM1: h = gelu(gather(x) @ W1 + b1)
        dim3 grid(MAXTILES, DFF / 128);
        k_mma<true><<<grid, 256, SMEM_TOTAL_MMA>>>(b1, b1);
    }
    {   // GEMM2: y = (h @ W2 + b2) * w
        dim3 grid(MAXTILES, DMODEL / 128);
        k_mma<false><<<grid, 256, SMEM_TOTAL_MMA>>>(g8k[0], g8k[1]);
    }
    k_combine<<<NTOK, 256>>>(out);
}

// round 16
// speedup vs baseline: 1.1827x; 1.0069x over previous
#include <cuda_runtime.h>
#include <cuda_fp16.h>
#include <math.h>
#include <stdint.h>

#define NTOK   8192
#define DMODEL 1024
#define DFF    4096
#define NEXP   8
#define MAXROWS 17408   // 136 tiles * 128
#define MAXTILES 136
#define RBLOCKS (NTOK / 8)

// ---------------- scratch (device symbols; never passed from host) -----------
__device__ __half g_x16[(size_t)NTOK * DMODEL];
__device__ __half g_w1t[(size_t)NEXP * DFF * DMODEL];   // [E][N=DFF][K=DMODEL]
__device__ __half g_w2t[(size_t)NEXP * DMODEL * DFF];   // [E][N=DMODEL][K=DFF]
__device__ __half g_h16[(size_t)MAXROWS * DFF];
__device__ float g_y[(size_t)MAXROWS * DMODEL];
__device__ int   g_assign_token[MAXROWS];
__device__ float g_assign_w[MAXROWS];
__device__ int   g_pos[NTOK * 2];
__device__ int   g_sel[NTOK * 2];
__device__ float g_wsel[NTOK * 2];
__device__ int   g_cnt[NEXP];
__device__ int   g_amax[NEXP];
__device__ float g_psum_part[RBLOCKS * NEXP];
__device__ int   g_fill[NEXP];
__device__ int   g_off[NEXP];
__device__ int   g_tile_expert[MAXTILES];
__device__ int   g_row_tiles;
__device__ int   g_wswap;   // 1 -> first 33M buffer is W2
__device__ int   g_gswap;   // 1 -> first 8192 buffer is b2

// ---------------- probes / init / router / prep / scatter --------------------
__global__ void k_probe(const float* __restrict__ A, const float* __restrict__ B,
                        int n, int which) {
    __shared__ float sa[256], sb[256];
    int tid = threadIdx.x;
    float a = 0.f, b = 0.f;
    for (int i = tid; i < n; i += 256) { a += fabsf(A[i]); b += fabsf(B[i]); }
    sa[tid] = a; sb[tid] = b;
    __syncthreads();
    for (int s = 128; s > 0; s >>= 1) {
        if (tid < s) { sa[tid] += sa[tid + s]; sb[tid] += sb[tid + s]; }
        __syncthreads();
    }
    if (tid == 0) {
        int f = (sa[0] < sb[0]) ? 1 : 0;
        if (which == 0) g_wswap = f; else g_gswap = f;
    }
}

__global__ void k_zero() {
    int i = blockIdx.x * blockDim.x + threadIdx.x;
    if (i < MAXROWS) { g_assign_token[i] = -1; g_assign_w[i] = 0.f; }
    if (i < NEXP) { g_cnt[i] = 0; g_amax[i] = 0; g_fill[i] = 0; }
}

// router: logits->softmax->top2 + aux stats; also emits x in fp16 (fused convx)
__global__ __launch_bounds__(256) void k_router(const float* __restrict__ x,
                                                const float* __restrict__ WgA,
                                                const float* __restrict__ WgB,
                                                const float* __restrict__ bg) {
    const float* Wg = g_gswap ? WgB : WgA;
    __shared__ float sW[NEXP][DMODEL];
    __shared__ float s_psum[NEXP];
    __shared__ int   s_amax[NEXP];
    __shared__ int   s_cnt[NEXP];
    int tid = threadIdx.x;
    for (int i = tid; i < DMODEL * NEXP; i += 256) sW[i & 7][i >> 3] = Wg[i];
    if (tid < NEXP) { s_psum[tid] = 0.f; s_amax[tid] = 0; s_cnt[tid] = 0; }
    __syncthreads();
    int warp = tid >> 5, lane = tid & 31;
    int t = blockIdx.x * 8 + warp;
    const float* xr = x + (size_t)t * DMODEL;
    __half* xo = g_x16 + (size_t)t * DMODEL;
    float acc[NEXP];
#pragma unroll
    for (int e = 0; e < NEXP; e++) acc[e] = 0.f;
    for (int j = 0; j < 32; j++) {
        float xv = xr[j * 32 + lane];
        xo[j * 32 + lane] = __float2half_rn(xv);
#pragma unroll
        for (int e = 0; e < NEXP; e++) acc[e] += xv * sW[e][j * 32 + lane];
    }
#pragma unroll
    for (int o = 16; o > 0; o >>= 1)
#pragma unroll
        for (int e = 0; e < NEXP; e++) acc[e] += __shfl_xor_sync(0xffffffffu, acc[e], o);
    if (lane == 0) {
        float l[NEXP], p[NEXP];
#pragma unroll
        for (int e = 0; e < NEXP; e++) l[e] = acc[e] + bg[e];
        float mx = l[0];
#pragma unroll
        for (int e = 1; e < NEXP; e++) mx = fmaxf(mx, l[e]);
        float s = 0.f;
#pragma unroll
        for (int e = 0; e < NEXP; e++) { p[e] = expf(l[e] - mx); s += p[e]; }
        float inv = 1.f / s;
#pragma unroll
        for (int e = 0; e < NEXP; e++) { p[e] *= inv; atomicAdd(&s_psum[e], p[e]); }
        int a1 = 0;
#pragma unroll
        for (int e = 1; e < NEXP; e++) if (p[e] > p[a1]) a1 = e;
        int a2 = -1;
#pragma unroll
        for (int e = 0; e < NEXP; e++) if (e != a1 && (a2 < 0 || p[e] > p[a2])) a2 = e;
        atomicAdd(&s_amax[a1], 1);
        atomicAdd(&s_cnt[a1], 1);
        atomicAdd(&s_cnt[a2], 1);
        float ws = 1.f / (p[a1] + p[a2]);
        g_sel[t * 2 + 0] = a1;  g_wsel[t * 2 + 0] = p[a1] * ws;
        g_sel[t * 2 + 1] = a2;  g_wsel[t * 2 + 1] = p[a2] * ws;
    }
    __syncthreads();
    if (tid < NEXP) {
        g_psum_part[blockIdx.x * NEXP + tid] = s_psum[tid];
        atomicAdd(&g_amax[tid], s_amax[tid]);
        atomicAdd(&g_cnt[tid], s_cnt[tid]);
    }
}

__global__ void k_prep(float* d_out, int out_size) {
    if (threadIdx.x == 0 && blockIdx.x == 0) {
        int off = 0, tiles = 0;
        for (int e = 0; e < NEXP; e++) {
            g_off[e] = off;
            int nt = (g_cnt[e] + 127) >> 7;
            for (int i = 0; i < nt; i++) g_tile_expert[tiles++] = e;
            off += nt * 128;
        }
        g_row_tiles = tiles;
        float aux = 0.f;
        for (int e = 0; e < NEXP; e++) {
            float pm = 0.f;
            for (int b = 0; b < RBLOCKS; b++) pm += g_psum_part[b * NEXP + e];
            aux += (pm / (float)NTOK) * ((float)g_amax[e] / (float)NTOK);
        }
        aux *= (float)NEXP;
        if (out_size > NTOK * DMODEL) d_out[(size_t)NTOK * DMODEL] = aux;
    }
}

__global__ void k_scatter() {
    int i = blockIdx.x * blockDim.x + threadIdx.x;
    if (i >= NTOK * 2) return;
    int t = i >> 1;
    int e = g_sel[i];
    int p = atomicAdd(&g_fill[e], 1);
    int row = g_off[e] + p;
    g_assign_token[row] = t;
    g_assign_w[row] = g_wsel[i];
    g_pos[i] = row;
}

// transpose W[E][K][N] fp32 -> [E][N][K] fp16, vectorized half2 writes.
// Tile: 64 k x 32 n per block, 256 threads.
template <bool PHASE1>
__global__ __launch_bounds__(256) void k_wtrans(const float* __restrict__ WA,
                                                const float* __restrict__ WB) {
    constexpr int K = PHASE1 ? DMODEL : DFF;
    constexpr int N = PHASE1 ? DFF : DMODEL;
    const float* W = PHASE1 ? (g_wswap ? WB : WA) : (g_wswap ? WA : WB);
    __half* O = PHASE1 ? g_w1t : g_w2t;
    int e = blockIdx.z;
    int n0 = blockIdx.x * 32, k0 = blockIdx.y * 64;
    __shared__ float t[64][33];
    int tid = threadIdx.x;
    int tx = tid & 31, ty = tid >> 5;          // tx: n, ty: k-group (8)
    const float* Wp = W + (size_t)e * K * N;
#pragma unroll
    for (int j = 0; j < 8; j++) {
        int k = ty + j * 8;
        t[k][tx] = Wp[(size_t)(k0 + k) * N + n0 + tx];
    }
    __syncthreads();
    // write: n = tid>>3 (32 rows), k covers 8 contiguous from (tid&7)*8
    int n = tid >> 3;
    int kb = (tid & 7) * 8;
    __half* Orow = O + ((size_t)e * N + n0 + n) * K + k0 + kb;
#pragma unroll
    for (int j = 0; j < 4; j++) {
        float v0 = t[kb + 2 * j][n];
        float v1 = t[kb + 2 * j + 1][n];
        *(__half2*)(Orow + 2 * j) = __halves2half2(__float2half_rn(v0), __float2half_rn(v1));
    }
}

// ---------------- PTX helpers ------------------------------------------------
__device__ __forceinline__ uint32_t smem_u32(const void* p) {
    uint32_t a;
    asm("{ .reg .u64 t; cvta.to.shared.u64 t, %1; cvt.u32.u64 %0, t; }" : "=r"(a) : "l"(p));
    return a;
}
__device__ __forceinline__ void cp16(uint32_t s, const void* g, uint32_t srcsize) {
    asm volatile("cp.async.cg.shared.global [%0], [%1], 16, %2;"
                 :: "r"(s), "l"(g), "r"(srcsize) : "memory");
}
#define CP_COMMIT() asm volatile("cp.async.commit_group;" ::: "memory")
#define CP_WAIT2()  asm volatile("cp.async.wait_group 2;" ::: "memory")
#define CP_WAIT0()  asm volatile("cp.async.wait_group 0;" ::: "memory")

__device__ __forceinline__ void ldm4(uint32_t& r0, uint32_t& r1, uint32_t& r2,
                                     uint32_t& r3, uint32_t addr) {
    asm volatile("ldmatrix.sync.aligned.m8n8.x4.shared.b16 {%0,%1,%2,%3}, [%4];"
                 : "=r"(r0), "=r"(r1), "=r"(r2), "=r"(r3) : "r"(addr));
}
__device__ __forceinline__ void mma16816(float* c, const uint32_t* a,
                                         uint32_t b0, uint32_t b1) {
    asm volatile(
        "mma.sync.aligned.m16n8k16.row.col.f32.f16.f16.f32 "
        "{%0,%1,%2,%3}, {%4,%5,%6,%7}, {%8,%9}, {%0,%1,%2,%3};"
        : "+f"(c[0]), "+f"(c[1]), "+f"(c[2]), "+f"(c[3])
        : "r"(a[0]), "r"(a[1]), "r"(a[2]), "r"(a[3]), "r"(b0), "r"(b1));
}

// ---------------- fp16 tensor-core grouped GEMM (R11-proven config) ----------
// CTA 128x128, 8 warps (4x2), warp tile 32x64, BK=32, 3-stage cp.async,
// ldmatrix fragment loads. smem row stride = 40 fp16 = 80 bytes.
// GRID AXES: blockIdx.x = COLUMN tile (fastest), blockIdx.y = row tile, so
// concurrent CTAs share one A row tile -> g_h16/g_x16 read ~once from DRAM.
#define ROWB 80
#define OFF_A 0
#define OFF_B 10240
#define BUF_B 20480
#define NSTAGE 3
#define SMEM_TOTAL_MMA (NSTAGE * BUF_B)   // 61440

template <bool PHASE1>
__global__ __launch_bounds__(256) void k_mma(const float* __restrict__ BiasA,
                                             const float* __restrict__ BiasB) {
    constexpr int KDIM = PHASE1 ? DMODEL : DFF;
    constexpr int NDIM = PHASE1 ? DFF : DMODEL;
    constexpr int NC = KDIM / 32;
    int tileRow = blockIdx.y;            // swapped: y = row tile
    if (tileRow >= g_row_tiles) return;
    int e = g_tile_expert[tileRow];
    int row0 = tileRow * 128;
    int col0 = blockIdx.x * 128;         // swapped: x = column tile (fastest)

    extern __shared__ char dsm[];
    __shared__ int s_tok[128];
    uint32_t smb = smem_u32(dsm);

    int tid = threadIdx.x;
    int w = tid >> 5, lane = tid & 31;
    int grp = lane >> 2, qid = lane & 3;
    int wr = w >> 1, wc = w & 1;
    int m0 = wr * 32, n0 = wc * 64;

    if (tid < 128) s_tok[tid] = g_assign_token[row0 + tid];

    const __half* A_base = PHASE1 ? g_x16 : g_h16;
    const __half* B_base = PHASE1 ? g_w1t : g_w2t;

    int lrow = tid >> 1;               // 0..127
    int lk   = (tid & 1) * 16;         // element offset 0 or 16

    float c[2][8][4];
#pragma unroll
    for (int i = 0; i < 2; i++)
#pragma unroll
        for (int j = 0; j < 8; j++)
#pragma unroll
            for (int q = 0; q < 4; q++) c[i][j][q] = 0.f;

    __syncthreads();                   // s_tok visible before gather loads

    // ---- chunk loader: 2x16B per array per thread (full 64B rows) ----
    auto load_chunk = [&](int cidx, int buf) {
        int k0 = cidx * 32;
        uint32_t sb = smb + buf * BUF_B;
        uint32_t so = (uint32_t)lrow * ROWB + lk * 2;   // byte offset 0 or 32
        size_t asrc; uint32_t vs = 16;
        if (PHASE1) {
            int tok = s_tok[lrow];
            if (tok < 0) { tok = 0; vs = 0; }
            asrc = (size_t)tok * KDIM + k0 + lk;
        } else {
            asrc = (size_t)(row0 + lrow) * KDIM + k0 + lk;
        }
        cp16(sb + OFF_A + so,      A_base + asrc,     vs);
        cp16(sb + OFF_A + so + 16, A_base + asrc + 8, vs);
        size_t bsrc = ((size_t)e * NDIM + col0 + lrow) * KDIM + k0 + lk;
        cp16(sb + OFF_B + so,      B_base + bsrc,     16);
        cp16(sb + OFF_B + so + 16, B_base + bsrc + 8, 16);
    };

    load_chunk(0, 0);
    CP_COMMIT();
    load_chunk(1, 1);
    CP_COMMIT();

    // per-lane ldmatrix address pieces
    uint32_t a_row = (uint32_t)(lane & 15);
    uint32_t a_koff = (uint32_t)((lane >> 4) * 8);
    uint32_t b_rowoff = (uint32_t)(((lane >> 4) & 1) * 8 + (lane & 7));
    uint32_t b_koff = (uint32_t)(((lane >> 3) & 1) * 8);

    for (int cidx = 0; cidx < NC; cidx++) {
        if (cidx + 2 < NC) load_chunk(cidx + 2, (cidx + 2) % NSTAGE);
        CP_COMMIT();           // uniform: one group per iteration (may be empty)
        CP_WAIT2();            // chunk cidx resident
        __syncthreads();

        uint32_t sb = smb + (cidx % NSTAGE) * BUF_B;
#pragma unroll
        for (int ks = 0; ks < 32; ks += 16) {
            uint32_t a[2][4];
#pragma unroll
            for (int mt = 0; mt < 2; mt++) {
                uint32_t ad = sb + OFF_A + (uint32_t)(m0 + mt * 16 + a_row) * ROWB
                            + (ks + a_koff) * 2;
                ldm4(a[mt][0], a[mt][1], a[mt][2], a[mt][3], ad);
            }
            uint32_t b[8][2];
#pragma unroll
            for (int np = 0; np < 4; np++) {
                uint32_t bd = sb + OFF_B + (uint32_t)(n0 + np * 16 + b_rowoff) * ROWB
                            + (ks + b_koff) * 2;
                ldm4(b[2 * np][0], b[2 * np][1], b[2 * np + 1][0],
                     b[2 * np + 1][1], bd);
            }
#pragma unroll
            for (int nt = 0; nt < 8; nt++)
#pragma unroll
                for (int mt = 0; mt < 2; mt++)
                    mma16816(c[mt][nt], a[mt], b[nt][0], b[nt][1]);
        }
        __syncthreads();   // all frag reads done before buffer reuse
    }
    CP_WAIT0();

    // ---- epilogue ----
    const float* Bias = PHASE1 ? BiasA : (g_gswap ? BiasA : BiasB);
#pragma unroll
    for (int mt = 0; mt < 2; mt++) {
        int rA = row0 + m0 + mt * 16 + grp;
        float sc0 = PHASE1 ? 1.f : g_assign_w[rA];
        float sc1 = PHASE1 ? 1.f : g_assign_w[rA + 8];
#pragma unroll
        for (int nt = 0; nt < 8; nt++) {
            int col = col0 + n0 + nt * 8 + qid * 2;
            float b0 = Bias[(size_t)e * NDIM + col];
            float b1v = Bias[(size_t)e * NDIM + col + 1];
            float v00 = c[mt][nt][0] + b0, v01 = c[mt][nt][1] + b1v;
            float v10 = c[mt][nt][2] + b0, v11 = c[mt][nt][3] + b1v;
            if (PHASE1) {
                v00 = 0.5f * v00 * (1.f + erff(v00 * 0.70710678118654752f));
                v01 = 0.5f * v01 * (1.f + erff(v01 * 0.70710678118654752f));
                v10 = 0.5f * v10 * (1.f + erff(v10 * 0.70710678118654752f));
                v11 = 0.5f * v11 * (1.f + erff(v11 * 0.70710678118654752f));
                size_t o0 = (size_t)rA * DFF + col;
                size_t o1 = (size_t)(rA + 8) * DFF + col;
                *(__half2*)(g_h16 + o0) = __halves2half2(__float2half_rn(v00), __float2half_rn(v01));
                *(__half2*)(g_h16 + o1) = __halves2half2(__float2half_rn(v10), __float2half_rn(v11));
            } else {
                size_t o0 = (size_t)rA * DMODEL + col;
                size_t o1 = (size_t)(rA + 8) * DMODEL + col;
                *(float2*)(g_y + o0) = make_float2(v00 * sc0, v01 * sc0);
                *(float2*)(g_y + o1) = make_float2(v10 * sc1, v11 * sc1);
            }
        }
    }
}

// ---------------- combine -----------------------------------------------------
__global__ void k_combine(float* __restrict__ out) {
    int t = blockIdx.x;
    int c = threadIdx.x;
    int p0 = g_pos[t * 2 + 0];
    int p1 = g_pos[t * 2 + 1];
    const float4* y0 = (const float4*)(g_y + (size_t)p0 * DMODEL);
    const float4* y1 = (const float4*)(g_y + (size_t)p1 * DMODEL);
    float4 a = y0[c], b = y1[c];
    ((float4*)(out + (size_t)t * DMODEL))[c] =
        make_float4(a.x + b.x, a.y + b.y, a.z + b.z, a.w + b.w);
}

// ---------------- launch -----------------------------------------------------
extern "C" void kernel_launch(void* const* d_in, const int* in_sizes, int n_in,
                              void* d_out, int out_size) {
    const float *x = nullptr, *bg = nullptr, *b1 = nullptr;
    const float *w33[2] = {nullptr, nullptr};
    const float *g8k[2] = {nullptr, nullptr};
    int n33 = 0, n8k = 0;
    for (int i = 0; i < n_in; i++) {
        int sz = in_sizes[i];
        const float* p = (const float*)d_in[i];
        if      (sz == NTOK * DMODEL)        x  = p;
        else if (sz == NEXP)                 bg = p;
        else if (sz == NEXP * DFF)           b1 = p;
        else if (sz == NEXP * DMODEL * DFF)  { if (n33 < 2) w33[n33++] = p; }
        else if (sz == DMODEL * NEXP)        { if (n8k < 2) g8k[n8k++] = p; }
    }
    float* out = (float*)d_out;

    cudaFuncSetAttribute(k_mma<true>,  cudaFuncAttributeMaxDynamicSharedMemorySize, SMEM_TOTAL_MMA);
    cudaFuncSetAttribute(k_mma<false>, cudaFuncAttributeMaxDynamicSharedMemorySize, SMEM_TOTAL_MMA);

    k_probe<<<1, 256>>>(w33[0], w33[1], 4096, 0);
    k_probe<<<1, 256>>>(g8k[0], g8k[1], 8192, 1);

    k_zero<<<(MAXROWS + 255) / 256, 256>>>();
    k_router<<<RBLOCKS, 256>>>(x, g8k[0], g8k[1], bg);
    k_prep<<<1, 32>>>(out, out_size);
    k_scatter<<<(NTOK * 2 + 255) / 256, 256>>>();

    {   // W1: [E][1024][4096] -> [E][4096][1024]
        dim3 g(DFF / 32, DMODEL / 64, NEXP);
        k_wtrans<true><<<g, 256>>>(w33[0], w33[1]);
    }
    {   // W2: [E][4096][1024] -> [E][1024][4096]
        dim3 g(DMODEL / 32, DFF / 64, NEXP);
        k_wtrans<false><<<g, 256>>>(w33[0], w33[1]);
    }

    {   // GEMM1: h = gelu(gather(x) @ W1 + b1)   grid: x=cols (fast), y=rows
        dim3 grid(DFF / 128, MAXTILES);
        k_mma<true><<<grid, 256, SMEM_TOTAL_MMA>>>(b1, b1);
    }
    {   // GEMM2: y = (h @ W2 + b2) * w           grid: x=cols (fast), y=rows
        dim3 grid(DMODEL / 128, MAXTILES);
        k_mma<false><<<grid, 256, SMEM_TOTAL_MMA>>>(g8k[0], g8k[1]);
    }
    k_combine<<<NTOK, 256>>>(out);
}